// round 3
// baseline (speedup 1.0000x reference)
#include <cuda_runtime.h>

#define B_ 8
#define C_ 64
#define H_ 64
#define W_ 512
#define HW_ (H_*W_)      // 32768
#define CHW_ (C_*H_*W_)  // 2097152

// ---------------- scratch (device globals; no runtime allocation) ----------------
__device__ float g_Gp[1024][4096];   // per (bh, w-half) partial Gram K·V^T
__device__ float g_skp[1024][64];    // partial channel sums of k
__device__ float g_svp[1024][64];    // partial channel sums of v
__device__ float g_P[512][4096];     // PT[i][c]  (P transposed)
__device__ float g_p0[512][64];      // output bias per bh
__device__ float g_A0[4096];         // Wq^T Wk
__device__ float g_a1[64];           // Wq^T bk
__device__ float g_w1[64];           // Wk^T bq
__device__ float g_sc;               // bk . bq

// ---------------- k2a: bh-independent precompute -------------------------------
__global__ __launch_bounds__(256) void k2a_pre(const float* __restrict__ Wq,
                                               const float* __restrict__ bq,
                                               const float* __restrict__ Wk,
                                               const float* __restrict__ bk) {
    __shared__ float sQ[64][65];
    __shared__ float sK[64][65];
    int t = threadIdx.x;
    for (int idx = t; idx < 4096; idx += 256) {
        sQ[idx >> 6][idx & 63] = Wq[idx];
        sK[idx >> 6][idx & 63] = Wk[idx];
    }
    __syncthreads();
    int r = t >> 2;
    int c0 = (t & 3) * 16;
    float acc[16];
#pragma unroll
    for (int c = 0; c < 16; c++) acc[c] = 0.f;
    for (int cc = 0; cc < 64; cc++) {
        float qv = sQ[cc][r];
#pragma unroll
        for (int c = 0; c < 16; c++) acc[c] += qv * sK[cc][c0 + c];
    }
#pragma unroll
    for (int c = 0; c < 16; c++) g_A0[r * 64 + c0 + c] = acc[c];
    if (t < 64) {
        float a1 = 0.f, w1 = 0.f;
        for (int cc = 0; cc < 64; cc++) {
            a1 += sQ[cc][t] * bk[cc];
            w1 += sK[cc][t] * bq[cc];
        }
        g_a1[t] = a1;
        g_w1[t] = w1;
    }
    if (t == 0) {
        float sc = 0.f;
        for (int cc = 0; cc < 64; cc++) sc += bk[cc] * bq[cc];
        g_sc = sc;
    }
}

// ---------------- k1: Gram matrix G = K V^T per (b,h), split over w halves -----
__global__ __launch_bounds__(128, 8) void k1_gram(const float* __restrict__ kin,
                                                  const float* __restrict__ vin) {
    __shared__ float sK[64][65];
    __shared__ float sV[64][65];
    int blk = blockIdx.x;
    int bh = blk >> 1;
    int s  = blk & 1;
    int b = bh >> 6, h = bh & 63;
    const float* kb = kin + (size_t)b * CHW_ + (size_t)h * W_ + s * 256;
    const float* vb = vin + (size_t)b * CHW_ + (size_t)h * W_ + s * 256;
    int t = threadIdx.x;
    int tx = t & 15, ty = t >> 4;
    float acc[8][4];
#pragma unroll
    for (int u = 0; u < 8; u++)
#pragma unroll
        for (int vj = 0; vj < 4; vj++) acc[u][vj] = 0.f;
    float rowsum = 0.f;

    for (int t0 = 0; t0 < 256; t0 += 64) {
        __syncthreads();
#pragma unroll
        for (int r = 0; r < 8; r++) {
            int e = t + 128 * r;
            int ch = e >> 4;
            int wg = e & 15;
            float4 k4 = *(const float4*)(kb + (size_t)ch * HW_ + t0 + wg * 4);
            float4 v4 = *(const float4*)(vb + (size_t)ch * HW_ + t0 + wg * 4);
            sK[ch][wg * 4 + 0] = k4.x; sK[ch][wg * 4 + 1] = k4.y;
            sK[ch][wg * 4 + 2] = k4.z; sK[ch][wg * 4 + 3] = k4.w;
            sV[ch][wg * 4 + 0] = v4.x; sV[ch][wg * 4 + 1] = v4.y;
            sV[ch][wg * 4 + 2] = v4.z; sV[ch][wg * 4 + 3] = v4.w;
        }
        __syncthreads();
        if (t < 64) {
#pragma unroll 8
            for (int w = 0; w < 64; w++) rowsum += sK[t][w];
        } else {
#pragma unroll 8
            for (int w = 0; w < 64; w++) rowsum += sV[t - 64][w];
        }
#pragma unroll 4
        for (int w = 0; w < 64; w++) {
            float a[8], bw[4];
#pragma unroll
            for (int u = 0; u < 8; u++) a[u] = sK[ty + 8 * u][w];
#pragma unroll
            for (int vj = 0; vj < 4; vj++) bw[vj] = sV[tx + 16 * vj][w];
#pragma unroll
            for (int u = 0; u < 8; u++)
#pragma unroll
                for (int vj = 0; vj < 4; vj++)
                    acc[u][vj] += a[u] * bw[vj];
        }
    }
    float* Gout = g_Gp[blk];
#pragma unroll
    for (int u = 0; u < 8; u++)
#pragma unroll
        for (int vj = 0; vj < 4; vj++)
            Gout[(ty + 8 * u) * 64 + tx + 16 * vj] = acc[u][vj];
    if (t < 64) g_skp[blk][t] = rowsum;
    else        g_svp[blk][t - 64] = rowsum;
}

// ---------------- k2: fused  T = A0*G  then  PT = T*Wv^T + rank-1 ; p0 ---------
// Shared-memory budget: X (G, later overwritten by T) + Y (A0, later Wv) only.
__global__ __launch_bounds__(256) void k2_fused(const float* __restrict__ Wv,
                                                const float* __restrict__ bv) {
    __shared__ float X[64][65];   // G  -> overwritten in place by T
    __shared__ float Y[64][65];   // A0 -> reloaded with Wv
    __shared__ float skv[64], svv[64], t2v[64], v1v[64], a1v[64], bvv[64], zv[64];
    __shared__ float s_skw1;
    int bh = blockIdx.x;
    int t = threadIdx.x;
    const float* G0 = g_Gp[bh * 2];
    const float* G1 = g_Gp[bh * 2 + 1];
    for (int idx = t; idx < 4096; idx += 256) {
        X[idx >> 6][idx & 63] = G0[idx] + G1[idx];
        Y[idx >> 6][idx & 63] = g_A0[idx];
    }
    if (t < 64) {
        skv[t] = g_skp[bh * 2][t] + g_skp[bh * 2 + 1][t];
        svv[t] = g_svp[bh * 2][t] + g_svp[bh * 2 + 1][t];
        bvv[t] = bv[t];
        a1v[t] = g_a1[t];
    }
    __syncthreads();

    int r = t >> 2, c0 = (t & 3) * 16;
    // Stage A: T = A0 * G  (accumulate in registers; G stays valid in X)
    float acc[16];
#pragma unroll
    for (int c = 0; c < 16; c++) acc[c] = 0.f;
    for (int kk = 0; kk < 64; kk++) {
        float yv = Y[r][kk];
#pragma unroll
        for (int c = 0; c < 16; c++) acc[c] += yv * X[kk][c0 + c];
    }
    if (t < 64) {
        float v1 = 0.f;
        for (int kk = 0; kk < 64; kk++) v1 += Y[t][kk] * skv[kk];
        v1v[t] = v1;
    } else if (t < 128) {
        int j = t - 64;
        float t2 = 0.f;
        for (int i = 0; i < 64; i++) t2 += X[i][j] * g_w1[i];
        t2v[j] = t2;
    } else if (t == 128) {
        float sw = 0.f;
        for (int kk = 0; kk < 64; kk++) sw += skv[kk] * g_w1[kk];
        s_skw1 = sw;
    }
    __syncthreads();   // all reads of G complete

    // Overwrite X with T; reload Y with Wv
#pragma unroll
    for (int c = 0; c < 16; c++) X[r][c0 + c] = acc[c];
    for (int idx = t; idx < 4096; idx += 256)
        Y[idx >> 6][idx & 63] = Wv[idx];
    __syncthreads();
    if (t < 64) {
        float z = 0.f;
        for (int j = 0; j < 64; j++) z += Y[t][j] * svv[j];
        zv[t] = z;
    }
    __syncthreads();

    // Stage B: PT = T * Wv^T + v1*bv^T + a1*(z + 512*bv)^T
#pragma unroll
    for (int c = 0; c < 16; c++) acc[c] = 0.f;
    for (int j = 0; j < 64; j++) {
        float xv = X[r][j];
#pragma unroll
        for (int c = 0; c < 16; c++) acc[c] += xv * Y[c0 + c][j];
    }
    {
        float* P = g_P[bh];
        float v1 = v1v[r], a1 = a1v[r];
#pragma unroll
        for (int c = 0; c < 16; c++) {
            int cp = c0 + c;
            P[r * 64 + cp] = acc[c] + v1 * bvv[cp] + a1 * (zv[cp] + 512.f * bvv[cp]);
        }
    }
    if (t < 64) {
        float p0 = 0.f;
        for (int j = 0; j < 64; j++) p0 += Y[t][j] * t2v[j];
        float sc = g_sc;
        p0 += s_skw1 * bvv[t] + sc * zv[t] + 512.f * sc * bvv[t];
        g_p0[bh][t] = p0;
    }
}

// ---------------- k3: out = P.q + p0 + residual --------------------------------
__global__ __launch_bounds__(128, 8) void k3_out(const float* __restrict__ qin,
                                                 float* __restrict__ out) {
    __shared__ float sPT[64][65];  // [i][c]
    __shared__ float sq[64][65];   // [ch][w_local]
    __shared__ float sp0[64];
    int blk = blockIdx.x;
    int bh = blk >> 1;
    int s = blk & 1;
    int b = bh >> 6, h = bh & 63;
    const float* qb = qin + (size_t)b * CHW_ + (size_t)h * W_ + s * 256;
    float* ob = out + (size_t)b * CHW_ + (size_t)h * W_ + s * 256;
    int t = threadIdx.x;
    int tx = t & 15, ty = t >> 4;

    for (int idx = t; idx < 4096; idx += 128)
        sPT[idx >> 6][idx & 63] = g_P[bh][idx];
    if (t < 64) sp0[t] = g_p0[bh][t];

    for (int t0 = 0; t0 < 256; t0 += 64) {
        __syncthreads();
#pragma unroll
        for (int r = 0; r < 8; r++) {
            int e = t + 128 * r;
            int ch = e >> 4, wg = e & 15;
            float4 q4 = *(const float4*)(qb + (size_t)ch * HW_ + t0 + wg * 4);
            sq[ch][wg * 4 + 0] = q4.x; sq[ch][wg * 4 + 1] = q4.y;
            sq[ch][wg * 4 + 2] = q4.z; sq[ch][wg * 4 + 3] = q4.w;
        }
        __syncthreads();
        float acc[8][4];
#pragma unroll
        for (int u = 0; u < 8; u++)
#pragma unroll
            for (int vj = 0; vj < 4; vj++) acc[u][vj] = 0.f;
#pragma unroll 4
        for (int i = 0; i < 64; i++) {
            float a[8], bw[4];
#pragma unroll
            for (int u = 0; u < 8; u++) a[u] = sPT[i][ty + 8 * u];
#pragma unroll
            for (int vj = 0; vj < 4; vj++) bw[vj] = sq[i][tx + 16 * vj];
#pragma unroll
            for (int u = 0; u < 8; u++)
#pragma unroll
                for (int vj = 0; vj < 4; vj++)
                    acc[u][vj] += a[u] * bw[vj];
        }
#pragma unroll
        for (int u = 0; u < 8; u++) {
            int c = ty + 8 * u;
            float p0c = sp0[c];
#pragma unroll
            for (int vj = 0; vj < 4; vj++) {
                int w = tx + 16 * vj;
                ob[(size_t)c * HW_ + t0 + w] = acc[u][vj] + p0c + sq[c][w];
            }
        }
    }
}

// ---------------- launch --------------------------------------------------------
extern "C" void kernel_launch(void* const* d_in, const int* in_sizes, int n_in,
                              void* d_out, int out_size) {
    const float* q  = (const float*)d_in[0];
    const float* k  = (const float*)d_in[1];
    const float* v  = (const float*)d_in[2];
    const float* Wq = (const float*)d_in[3];
    const float* bq = (const float*)d_in[4];
    const float* Wk = (const float*)d_in[5];
    const float* bk = (const float*)d_in[6];
    const float* Wv = (const float*)d_in[7];
    const float* bv = (const float*)d_in[8];
    float* out = (float*)d_out;

    k2a_pre<<<1, 256>>>(Wq, bq, Wk, bk);
    k1_gram<<<1024, 128>>>(k, v);
    k2_fused<<<512, 256>>>(Wv, bv);
    k3_out<<<1024, 128>>>(q, out);
}

// round 4
// speedup vs baseline: 1.0660x; 1.0660x over previous
#include <cuda_runtime.h>

#define B_ 8
#define C_ 64
#define H_ 64
#define W_ 512
#define HW_ (H_*W_)      // 32768
#define CHW_ (C_*H_*W_)  // 2097152

typedef unsigned long long ull;

// packed f32x2 helpers (Blackwell FFMA2 path)
#define FMA2(d, a, b) asm("fma.rn.f32x2 %0, %1, %2, %0;" : "+l"(d) : "l"(a), "l"(b))
#define PACK2(d, x)   asm("mov.b64 %0, {%1, %1};" : "=l"(d) : "r"(__float_as_uint(x)))
#define UNPACK2(lo, hi, v) asm("mov.b64 {%0, %1}, %2;" : "=r"(lo), "=r"(hi) : "l"(v))

// ---------------- scratch (device globals; no runtime allocation) ----------------
__device__ float g_Gp[2048][4096];   // per (bh, s, sub) partial Gram K·V^T
__device__ float g_skp[1024][64];    // partial channel sums of k (per blk)
__device__ float g_svp[1024][64];    // partial channel sums of v
__device__ float g_P[512][4096];     // PT[i][c]  (P transposed)
__device__ float g_p0[512][64];      // output bias per bh
__device__ float g_A0[4096];         // Wq^T Wk
__device__ float g_a1[64];           // Wq^T bk
__device__ float g_w1[64];           // Wk^T bq
__device__ float g_sc;               // bk . bq

// ---------------- k2a: bh-independent precompute -------------------------------
__global__ __launch_bounds__(256) void k2a_pre(const float* __restrict__ Wq,
                                               const float* __restrict__ bq,
                                               const float* __restrict__ Wk,
                                               const float* __restrict__ bk) {
    __shared__ float sQ[64][65];
    __shared__ float sK[64][65];
    int t = threadIdx.x;
    for (int idx = t; idx < 4096; idx += 256) {
        sQ[idx >> 6][idx & 63] = Wq[idx];
        sK[idx >> 6][idx & 63] = Wk[idx];
    }
    __syncthreads();
    int r = t >> 2;
    int c0 = (t & 3) * 16;
    float acc[16];
#pragma unroll
    for (int c = 0; c < 16; c++) acc[c] = 0.f;
    for (int cc = 0; cc < 64; cc++) {
        float qv = sQ[cc][r];
#pragma unroll
        for (int c = 0; c < 16; c++) acc[c] += qv * sK[cc][c0 + c];
    }
#pragma unroll
    for (int c = 0; c < 16; c++) g_A0[r * 64 + c0 + c] = acc[c];
    if (t < 64) {
        float a1 = 0.f, w1 = 0.f;
        for (int cc = 0; cc < 64; cc++) {
            a1 += sQ[cc][t] * bk[cc];
            w1 += sK[cc][t] * bq[cc];
        }
        g_a1[t] = a1;
        g_w1[t] = w1;
    }
    if (t == 0) {
        float sc = 0.f;
        for (int cc = 0; cc < 64; cc++) sc += bk[cc] * bq[cc];
        g_sc = sc;
    }
}

// ---------------- k1: Gram G = K V^T per (b,h); f32x2, transposed K tile -------
// grid 1024 = bh*2 + s(half of w). Block: 128 threads = 2 subs of 64.
// Each sub computes full 64x64 G over its 32-w slice of each 64-w chunk.
__global__ __launch_bounds__(128) void k1_gram(const float* __restrict__ kin,
                                               const float* __restrict__ vin) {
    __shared__ float sKt[64][66];   // [w][ck] transposed (pitch 66: 8B-aligned pairs)
    __shared__ float sV[64][68];    // [cv][w]  (pitch 68: 16B-aligned rows)
    int blk = blockIdx.x;
    int bh = blk >> 1, s = blk & 1;
    int b = bh >> 6, h = bh & 63;
    const float* kb = kin + (size_t)b * CHW_ + (size_t)h * W_ + s * 256;
    const float* vb = vin + (size_t)b * CHW_ + (size_t)h * W_ + s * 256;
    int t = threadIdx.x;
    int sub = t >> 6, t64 = t & 63;
    int tx = t64 & 7, ty = t64 >> 3;     // tile: ck = ty*8 + 2p + half, cv = tx + 8j

    ull acc[4][8];
#pragma unroll
    for (int p = 0; p < 4; p++)
#pragma unroll
        for (int j = 0; j < 8; j++) acc[p][j] = 0ull;
    float rs = 0.f;   // t<64: rowsum_k[ch=t]; t>=64: rowsum_v[ch=t-64]

    for (int t0 = 0; t0 < 256; t0 += 64) {
        __syncthreads();
#pragma unroll
        for (int r = 0; r < 8; r++) {
            int idx = t + 128 * r;        // 1024 float4 units = 64ch x 16wg
            int ch = idx >> 4, wg = idx & 15;
            float4 k4 = *(const float4*)(kb + (size_t)ch * HW_ + t0 + wg * 4);
            int wl = wg * 4;
            sKt[wl + 0][ch] = k4.x; sKt[wl + 1][ch] = k4.y;
            sKt[wl + 2][ch] = k4.z; sKt[wl + 3][ch] = k4.w;
            float4 v4 = *(const float4*)(vb + (size_t)ch * HW_ + t0 + wg * 4);
            *(float4*)&sV[ch][wl] = v4;
        }
        __syncthreads();
        // rowsums over the whole 64-w chunk
        if (t < 64) {
#pragma unroll 8
            for (int w = 0; w < 64; w++) rs += sKt[w][t];
        } else {
#pragma unroll 8
            for (int w = 0; w < 64; w++) rs += sV[t - 64][w];
        }
        // compute: sub's 32-w slice
        int wb = sub * 32;
#pragma unroll 2
        for (int w = wb; w < wb + 32; w++) {
            ull a[4];
#pragma unroll
            for (int p = 0; p < 4; p++)
                a[p] = *(const ull*)&sKt[w][ty * 8 + 2 * p];
#pragma unroll
            for (int j = 0; j < 8; j++) {
                float bvs = sV[tx + 8 * j][w];
                ull br; PACK2(br, bvs);
#pragma unroll
                for (int p = 0; p < 4; p++) FMA2(acc[p][j], a[p], br);
            }
        }
    }
    // write partial G
    float* G = g_Gp[blk * 2 + sub];
#pragma unroll
    for (int p = 0; p < 4; p++)
#pragma unroll
        for (int j = 0; j < 8; j++) {
            unsigned lo, hi;
            UNPACK2(lo, hi, acc[p][j]);
            int cv = tx + 8 * j;
            int ck = ty * 8 + 2 * p;
            G[ck * 64 + cv]       = __uint_as_float(lo);
            G[(ck + 1) * 64 + cv] = __uint_as_float(hi);
        }
    if (t < 64) g_skp[blk][t] = rs;
    else        g_svp[blk][t - 64] = rs;
}

// ---------------- k2: fused  T = A0*G  then  PT = T*Wv^T + rank-1 ; p0 ---------
__global__ __launch_bounds__(256) void k2_fused(const float* __restrict__ Wv,
                                                const float* __restrict__ bv) {
    __shared__ float X[64][65];   // G  -> overwritten in place by T
    __shared__ float Y[64][65];   // A0 -> reloaded with Wv
    __shared__ float skv[64], svv[64], t2v[64], v1v[64], a1v[64], bvv[64], zv[64];
    __shared__ float s_skw1;
    int bh = blockIdx.x;
    int t = threadIdx.x;
    const float* G0 = g_Gp[bh * 4 + 0];
    const float* G1 = g_Gp[bh * 4 + 1];
    const float* G2 = g_Gp[bh * 4 + 2];
    const float* G3 = g_Gp[bh * 4 + 3];
    for (int idx = t; idx < 4096; idx += 256) {
        X[idx >> 6][idx & 63] = (G0[idx] + G1[idx]) + (G2[idx] + G3[idx]);
        Y[idx >> 6][idx & 63] = g_A0[idx];
    }
    if (t < 64) {
        skv[t] = g_skp[bh * 2][t] + g_skp[bh * 2 + 1][t];
        svv[t] = g_svp[bh * 2][t] + g_svp[bh * 2 + 1][t];
        bvv[t] = bv[t];
        a1v[t] = g_a1[t];
    }
    __syncthreads();

    int r = t >> 2, c0 = (t & 3) * 16;
    float acc[16];
#pragma unroll
    for (int c = 0; c < 16; c++) acc[c] = 0.f;
    for (int kk = 0; kk < 64; kk++) {
        float yv = Y[r][kk];
#pragma unroll
        for (int c = 0; c < 16; c++) acc[c] += yv * X[kk][c0 + c];
    }
    if (t < 64) {
        float v1 = 0.f;
        for (int kk = 0; kk < 64; kk++) v1 += Y[t][kk] * skv[kk];
        v1v[t] = v1;
    } else if (t < 128) {
        int j = t - 64;
        float t2 = 0.f;
        for (int i = 0; i < 64; i++) t2 += X[i][j] * g_w1[i];
        t2v[j] = t2;
    } else if (t == 128) {
        float sw = 0.f;
        for (int kk = 0; kk < 64; kk++) sw += skv[kk] * g_w1[kk];
        s_skw1 = sw;
    }
    __syncthreads();   // all reads of G complete

#pragma unroll
    for (int c = 0; c < 16; c++) X[r][c0 + c] = acc[c];
    for (int idx = t; idx < 4096; idx += 256)
        Y[idx >> 6][idx & 63] = Wv[idx];
    __syncthreads();
    if (t < 64) {
        float z = 0.f;
        for (int j = 0; j < 64; j++) z += Y[t][j] * svv[j];
        zv[t] = z;
    }
    __syncthreads();

#pragma unroll
    for (int c = 0; c < 16; c++) acc[c] = 0.f;
    for (int j = 0; j < 64; j++) {
        float xv = X[r][j];
#pragma unroll
        for (int c = 0; c < 16; c++) acc[c] += xv * Y[c0 + c][j];
    }
    {
        float* P = g_P[bh];
        float v1 = v1v[r], a1 = a1v[r];
#pragma unroll
        for (int c = 0; c < 16; c++) {
            int cp = c0 + c;
            P[r * 64 + cp] = acc[c] + v1 * bvv[cp] + a1 * (zv[cp] + 512.f * bvv[cp]);
        }
    }
    if (t < 64) {
        float p0 = 0.f;
        for (int j = 0; j < 64; j++) p0 += Y[t][j] * t2v[j];
        float sc = g_sc;
        p0 += s_skw1 * bvv[t] + sc * zv[t] + 512.f * sc * bvv[t];
        g_p0[bh][t] = p0;
    }
}

// ---------------- k3: out = P.q + p0 + residual  (f32x2, 8x8 tiles) ------------
// grid 1024 = bh*2 + s; 256 threads; block covers 64c x 256w; dynamic smem.
__global__ __launch_bounds__(256) void k3_out(const float* __restrict__ qin,
                                              float* __restrict__ out) {
    extern __shared__ float dyn[];
    float (*sPT)[64] = (float(*)[64])dyn;              // 64 x 64 (16 KB)
    float (*sq)[256] = (float(*)[256])(dyn + 4096);    // 64 x 256 (64 KB)
    float* sp0 = dyn + 4096 + 16384;
    int blk = blockIdx.x;
    int bh = blk >> 1, s = blk & 1;
    int b = bh >> 6, h = bh & 63;
    const float* qb = qin + (size_t)b * CHW_ + (size_t)h * W_ + s * 256;
    float* ob = out + (size_t)b * CHW_ + (size_t)h * W_ + s * 256;
    int t = threadIdx.x;
    int tx = t & 31, ty = t >> 5;      // c0 = ty*8, w0 = tx*8

    for (int idx = t; idx < 1024; idx += 256) {        // sPT: 1024 float4
        int i = idx >> 4, c4 = (idx & 15) * 4;
        *(float4*)&sPT[i][c4] = *(const float4*)&g_P[bh][i * 64 + c4];
    }
    if (t < 64) sp0[t] = g_p0[bh][t];
    for (int idx = t; idx < 4096; idx += 256) {        // sq: 4096 float4
        int ch = idx >> 6, wg = (idx & 63) * 4;
        *(float4*)&sq[ch][wg] = *(const float4*)(qb + (size_t)ch * HW_ + wg);
    }
    __syncthreads();

    int c0 = ty * 8, w0 = tx * 8;
    ull acc[4][8];
#pragma unroll
    for (int p = 0; p < 4; p++)
#pragma unroll
        for (int j = 0; j < 8; j++) acc[p][j] = 0ull;

#pragma unroll 2
    for (int i = 0; i < 64; i++) {
        ull a[4];
        {
            const ull* ap = (const ull*)&sPT[i][c0];
            a[0] = ap[0]; a[1] = ap[1]; a[2] = ap[2]; a[3] = ap[3];
        }
        float4 b0 = *(const float4*)&sq[i][w0];
        float4 b1 = *(const float4*)&sq[i][w0 + 4];
        ull br[8];
        PACK2(br[0], b0.x); PACK2(br[1], b0.y); PACK2(br[2], b0.z); PACK2(br[3], b0.w);
        PACK2(br[4], b1.x); PACK2(br[5], b1.y); PACK2(br[6], b1.z); PACK2(br[7], b1.w);
#pragma unroll
        for (int j = 0; j < 8; j++)
#pragma unroll
            for (int p = 0; p < 4; p++) FMA2(acc[p][j], a[p], br[j]);
    }

    // writeout: rows c0+2p (+1), cols w0..w0+7, plus p0 and residual q
#pragma unroll
    for (int p = 0; p < 4; p++) {
        int ce = c0 + 2 * p;
        float oe[8], oh[8];
#pragma unroll
        for (int j = 0; j < 8; j++) {
            unsigned lo, hi;
            UNPACK2(lo, hi, acc[p][j]);
            oe[j] = __uint_as_float(lo);
            oh[j] = __uint_as_float(hi);
        }
        float pe = sp0[ce], ph = sp0[ce + 1];
#pragma unroll
        for (int j = 0; j < 8; j++) {
            oe[j] += pe + sq[ce][w0 + j];
            oh[j] += ph + sq[ce + 1][w0 + j];
        }
        float* oute = ob + (size_t)ce * HW_ + w0;
        float* outh = ob + (size_t)(ce + 1) * HW_ + w0;
        *(float4*)(oute)     = make_float4(oe[0], oe[1], oe[2], oe[3]);
        *(float4*)(oute + 4) = make_float4(oe[4], oe[5], oe[6], oe[7]);
        *(float4*)(outh)     = make_float4(oh[0], oh[1], oh[2], oh[3]);
        *(float4*)(outh + 4) = make_float4(oh[4], oh[5], oh[6], oh[7]);
    }
}

// ---------------- launch --------------------------------------------------------
extern "C" void kernel_launch(void* const* d_in, const int* in_sizes, int n_in,
                              void* d_out, int out_size) {
    const float* q  = (const float*)d_in[0];
    const float* k  = (const float*)d_in[1];
    const float* v  = (const float*)d_in[2];
    const float* Wq = (const float*)d_in[3];
    const float* bq = (const float*)d_in[4];
    const float* Wk = (const float*)d_in[5];
    const float* bk = (const float*)d_in[6];
    const float* Wv = (const float*)d_in[7];
    const float* bv = (const float*)d_in[8];
    float* out = (float*)d_out;

    const int k3_smem = (4096 + 16384 + 64) * 4;   // 82176 B
    cudaFuncSetAttribute(k3_out, cudaFuncAttributeMaxDynamicSharedMemorySize, k3_smem);

    k2a_pre<<<1, 256>>>(Wq, bq, Wk, bk);
    k1_gram<<<1024, 128>>>(k, v);
    k2_fused<<<512, 256>>>(Wv, bv);
    k3_out<<<1024, 256, k3_smem>>>(q, out);
}